// round 10
// baseline (speedup 1.0000x reference)
#include <cuda_runtime.h>
#include <cuda_fp16.h>
#include <math.h>
#include <stdint.h>

// Problem constants (B=2,S=2048,H=1024,E=64,K=8,F=512,cap=2.0)
#define TOK   4096
#define HD    1024
#define NE    64
#define KSEL  8
#define FF    512
#define NA    (TOK*KSEL)
#define CAP   1024

// ---------------- scratch (__device__ globals) ----------------
__device__ __align__(16) float g_logits[(size_t)TOK * NE];
__device__ int   g_rowtok[NE * CAP];
__device__ float g_wslot[NE * CAP];
__device__ int   g_cnt[NE];
__device__ __align__(16) __half g_xh [(size_t)TOK * HD];            // 8MB
__device__ __align__(16) __half g_w1h[(size_t)NE * HD * FF];        // 64MB
__device__ __align__(16) __half g_w3h[(size_t)NE * HD * FF];        // 64MB
__device__ __align__(16) __half g_w2h[(size_t)NE * FF * HD];        // 64MB
__device__ __align__(16) __half g_act[(size_t)NE * CAP * FF];       // 64MB

// ---------------- helpers ----------------
__device__ __forceinline__ uint32_t smem_u32(const void* p) {
    uint32_t a;
    asm("{ .reg .u64 t; cvta.to.shared.u64 t, %1; cvt.u32.u64 %0, t; }" : "=r"(a) : "l"(p));
    return a;
}
__device__ __forceinline__ void cpa16(uint32_t s, const void* g) {
    asm volatile("cp.async.cg.shared.global [%0], [%1], 16;" :: "r"(s), "l"(g));
}
#define CP_COMMIT() asm volatile("cp.async.commit_group;" ::: "memory")
#define CP_WAIT0()  asm volatile("cp.async.wait_group 0;" ::: "memory")
__device__ __forceinline__ void ldsm4(uint32_t* r, uint32_t addr) {
    asm volatile("ldmatrix.sync.aligned.m8n8.x4.shared.b16 {%0,%1,%2,%3}, [%4];"
                 : "=r"(r[0]), "=r"(r[1]), "=r"(r[2]), "=r"(r[3]) : "r"(addr));
}
__device__ __forceinline__ void ldsm4t(uint32_t* r, uint32_t addr) {
    asm volatile("ldmatrix.sync.aligned.m8n8.x4.trans.shared.b16 {%0,%1,%2,%3}, [%4];"
                 : "=r"(r[0]), "=r"(r[1]), "=r"(r[2]), "=r"(r[3]) : "r"(addr));
}
__device__ __forceinline__ void mma16816(float* c, const uint32_t* a, const uint32_t* b) {
    asm volatile("mma.sync.aligned.m16n8k16.row.col.f32.f16.f16.f32 "
                 "{%0,%1,%2,%3}, {%4,%5,%6,%7}, {%8,%9}, {%0,%1,%2,%3};"
                 : "+f"(c[0]), "+f"(c[1]), "+f"(c[2]), "+f"(c[3])
                 : "r"(a[0]), "r"(a[1]), "r"(a[2]), "r"(a[3]), "r"(b[0]), "r"(b[1]));
}
__device__ __forceinline__ uint32_t pkh(float a, float b) {
    __half2 h = __floats2half2_rn(a, b);
    return *(uint32_t*)&h;
}
__device__ __forceinline__ void red2(float* p, float a, float b) {
    asm volatile("red.global.add.v2.f32 [%0], {%1, %2};" :: "l"(p), "f"(a), "f"(b) : "memory");
}

// smem layouts (bytes), 2 stages, BK=64. A rows 144B; gemm_a B rows 144B; gemm_b B rows 272B.
#define GA_A(s)   ((s) * 18432)
#define GA_B1(s)  (36864 + (s) * 9216)
#define GA_B3(s)  (55296 + (s) * 9216)
#define GA_TOTAL  73728
#define GB_A(s)   ((s) * 18432)
#define GB_B(s)   (36864 + (s) * 17408)
#define GB_TOTAL  71680

// ---------------- 1) router logits + fp16 conversions (fused) ----------------
#define RT 8
#define RB (TOK / RT)          // 512 router blocks
#define CVB 1536               // conversion blocks
__global__ __launch_bounds__(256) void router_cvt_kernel(const float* __restrict__ x,
                                                         const float* __restrict__ wg,
                                                         const float* __restrict__ w1,
                                                         const float* __restrict__ w3,
                                                         const float* __restrict__ w2) {
    if (blockIdx.x >= RB) {
        const size_t N4 = (size_t)NE * HD * FF / 4;
        size_t i = (size_t)(blockIdx.x - RB) * 256 + threadIdx.x;
        size_t stride = (size_t)CVB * 256;
        for (; i < N4; i += stride) {
            float4 v = ((const float4*)w1)[i];
            ((uint2*)g_w1h)[i] = make_uint2(pkh(v.x, v.y), pkh(v.z, v.w));
            v = ((const float4*)w3)[i];
            ((uint2*)g_w3h)[i] = make_uint2(pkh(v.x, v.y), pkh(v.z, v.w));
            v = ((const float4*)w2)[i];
            ((uint2*)g_w2h)[i] = make_uint2(pkh(v.x, v.y), pkh(v.z, v.w));
        }
        return;
    }
    if (blockIdx.x == 0 && threadIdx.x < NE) g_cnt[threadIdx.x] = 0;
    __shared__ __align__(16) float xs[RT][HD];
    int t0 = blockIdx.x * RT;
    for (int i = threadIdx.x; i < RT * HD / 4; i += 256) {
        int r = i >> 8;
        int c = (i & 255) << 2;
        float4 v = *(const float4*)&x[(size_t)(t0 + r) * HD + c];
        *(float4*)&xs[r][c] = v;
        *(uint2*)&g_xh[(size_t)(t0 + r) * HD + c] = make_uint2(pkh(v.x, v.y), pkh(v.z, v.w));
    }
    __syncthreads();
    int e  = threadIdx.x & 63;
    int tg = threadIdx.x >> 6;
    float acc0 = 0.f, acc1 = 0.f;
#pragma unroll 4
    for (int j = 0; j < HD; ++j) {
        float w = wg[(size_t)j * NE + e];
        acc0 += w * xs[tg * 2 + 0][j];
        acc1 += w * xs[tg * 2 + 1][j];
    }
    g_logits[(size_t)(t0 + tg * 2 + 0) * NE + e] = acc0;
    g_logits[(size_t)(t0 + tg * 2 + 1) * NE + e] = acc1;
}

// ---------------- 2) topk + fused dispatch + zero_out (extra blocks) ----------------
#define TKB (TOK / 256)        // 16 topk blocks
#define ZOB (TOK * HD / 4 / 256)
__global__ __launch_bounds__(256) void topk_disp_zero_kernel(float4* __restrict__ outz) {
    if (blockIdx.x >= TKB) {
        int i = (blockIdx.x - TKB) * 256 + threadIdx.x;
        outz[i] = make_float4(0.f, 0.f, 0.f, 0.f);
        return;
    }
    int t = blockIdx.x * 256 + threadIdx.x;
    const float* l = g_logits + (size_t)t * NE;
    float m = -INFINITY;
    for (int e = 0; e < NE; ++e) m = fmaxf(m, l[e]);
    float s = 0.f;
    for (int e = 0; e < NE; ++e) s += expf(l[e] - m);
    unsigned long long mask = 0ull;
    float wv[KSEL]; int se[KSEL];
    float wsum = 0.f;
    for (int k = 0; k < KSEL; ++k) {
        float best = -INFINITY; int be = 0;
        for (int e = 0; e < NE; ++e) {
            if ((mask >> e) & 1ull) continue;
            float v = l[e];
            if (v > best) { best = v; be = e; }
        }
        mask |= (1ull << be);
        float p = expf(best - m) / s;
        wv[k] = p; se[k] = be; wsum += p;
    }
    float inv = 1.f / wsum;
    // fused dispatch: atomic rank per assignment (order-free; no drops at CAP=2x)
    for (int k = 0; k < KSEL; ++k) {
        int e = se[k];
        int p = atomicAdd(&g_cnt[e], 1);
        if (p < CAP) {
            g_rowtok[e * CAP + p] = t;
            g_wslot[e * CAP + p]  = wv[k] * inv;
        }
    }
}

// ---------------- 3) GEMM-A: act = silu(x@w1)*(x@w3)  [fp16 mma, BK=64, 2-stage, 2 CTA/SM] ----------------
// block 128m x 64n x BK64; 8 warps = 4m x 2n; warp tile 32x32 (dual acc)
__global__ __launch_bounds__(256, 2) void gemm_a_mma() {
    extern __shared__ char smc[];
    const uint32_t sb = smem_u32(smc);

    const int e = blockIdx.z;
    int cnt = g_cnt[e]; if (cnt > CAP) cnt = CAP;
    const int m_base = blockIdx.y * 128;
    if (m_base >= cnt) return;
    const int n_base = blockIdx.x * 64;

    const int tid = threadIdx.x, lane = tid & 31, wid = tid >> 5;
    const int wm = wid >> 1, wn = wid & 1;

    // A loads: 128 rows x 64k; thread: row=tid>>1, half=tid&1 (32 halves = 64B)
    const int arow = tid >> 1, ahalf = tid & 1;
    int gr = m_base + arow; if (gr >= cnt) gr = cnt - 1;
    const __half* xr = g_xh + (size_t)g_rowtok[e * CAP + gr] * HD + ahalf * 32;
    // B loads: 64 k-rows x 64n; thread: bk=tid>>2, bc=tid&3 (2 chunks of 16B per matrix)
    const int bk = tid >> 2, bc = tid & 3;

    const uint32_t aoff = (uint32_t)(wm * 32 + (lane & 15)) * 144 + (uint32_t)(lane >> 4) * 16;
    const uint32_t boff = (uint32_t)(lane & 15) * 144 + (uint32_t)(lane >> 4) * 16 + (uint32_t)wn * 64;

    float acc1[2][4][4] = {}, acc3[2][4][4] = {};

    auto issue = [&](int cc) {
        int s = cc & 1, k0 = cc * 64;
        uint32_t ad = sb + GA_A(s) + (uint32_t)arow * 144 + (uint32_t)ahalf * 64;
#pragma unroll
        for (int j = 0; j < 4; ++j) cpa16(ad + j * 16, xr + k0 + j * 8);
        size_t ro = ((size_t)e * HD + k0 + bk) * FF + n_base;
        uint32_t b1d = sb + GA_B1(s) + (uint32_t)bk * 144;
        uint32_t b3d = sb + GA_B3(s) + (uint32_t)bk * 144;
#pragma unroll
        for (int q = 0; q < 2; ++q) {
            cpa16(b1d + (bc + q * 4) * 16, g_w1h + ro + (bc + q * 4) * 8);
            cpa16(b3d + (bc + q * 4) * 16, g_w3h + ro + (bc + q * 4) * 8);
        }
    };

    issue(0); CP_COMMIT();

    for (int c = 0; c < HD / 64; ++c) {
        CP_WAIT0();
        __syncthreads();
        if (c + 1 < HD / 64) issue(c + 1);
        CP_COMMIT();
        const int s = c & 1;
        const uint32_t aS = sb + GA_A(s), b1S = sb + GA_B1(s), b3S = sb + GA_B3(s);
#pragma unroll
        for (int ks = 0; ks < 4; ++ks) {
            uint32_t a[2][4];
#pragma unroll
            for (int mf = 0; mf < 2; ++mf)
                ldsm4(a[mf], aS + aoff + (uint32_t)mf * (16 * 144) + (uint32_t)ks * 32);
#pragma unroll
            for (int pr = 0; pr < 2; ++pr) {
                uint32_t o = boff + (uint32_t)ks * (16 * 144) + (uint32_t)pr * 32;
                uint32_t b1[4], b3[4];
                ldsm4t(b1, b1S + o); ldsm4t(b3, b3S + o);
#pragma unroll
                for (int sub = 0; sub < 2; ++sub) {
                    int nf = pr * 2 + sub;
#pragma unroll
                    for (int mf = 0; mf < 2; ++mf) {
                        mma16816(acc1[mf][nf], a[mf], b1 + sub * 2);
                        mma16816(acc3[mf][nf], a[mf], b3 + sub * 2);
                    }
                }
            }
        }
    }

    // epilogue: silu(g)*u -> fp16 act
#pragma unroll
    for (int mf = 0; mf < 2; ++mf) {
#pragma unroll
        for (int half = 0; half < 2; ++half) {
            int r = wm * 32 + mf * 16 + (lane >> 2) + half * 8;
            int grr = m_base + r;
            if (grr < cnt) {
                size_t rb = ((size_t)e * CAP + grr) * FF + n_base + wn * 32 + (lane & 3) * 2;
#pragma unroll
                for (int nf = 0; nf < 4; ++nf) {
                    float g0 = acc1[mf][nf][half * 2],     u0 = acc3[mf][nf][half * 2];
                    float g1 = acc1[mf][nf][half * 2 + 1], u1 = acc3[mf][nf][half * 2 + 1];
                    float a0 = (g0 / (1.f + expf(-g0))) * u0;
                    float a1 = (g1 / (1.f + expf(-g1))) * u1;
                    *(uint32_t*)&g_act[rb + nf * 8] = pkh(a0, a1);
                }
            }
        }
    }
}

// ---------------- 4) GEMM-B: out += w * (act @ w2)  [fp16 mma, BK=64, 2-stage, red.v2 scatter] ----------------
// block 128m x 128n x BK64; 8 warps = 4m x 2n; warp tile 32x64
__global__ __launch_bounds__(256, 2) void gemm_b_mma(float* __restrict__ out) {
    extern __shared__ char smc[];
    const uint32_t sb = smem_u32(smc);

    const int e = blockIdx.z;
    int cnt = g_cnt[e]; if (cnt > CAP) cnt = CAP;
    const int m_base = blockIdx.y * 128;
    if (m_base >= cnt) return;
    const int n_base = blockIdx.x * 128;

    const int tid = threadIdx.x, lane = tid & 31, wid = tid >> 5;
    const int wm = wid >> 1, wn = wid & 1;

    const int arow = tid >> 1, ahalf = tid & 1;
    int gr = m_base + arow; if (gr >= cnt) gr = cnt - 1;
    const __half* ar = g_act + ((size_t)e * CAP + gr) * FF + ahalf * 32;
    const int bk = tid >> 2, bc = tid & 3;

    const uint32_t aoff = (uint32_t)(wm * 32 + (lane & 15)) * 144 + (uint32_t)(lane >> 4) * 16;
    const uint32_t boff = (uint32_t)(lane & 15) * 272 + (uint32_t)(lane >> 4) * 16 + (uint32_t)wn * 128;

    float acc[2][8][4] = {};

    auto issue = [&](int cc) {
        int s = cc & 1, k0 = cc * 64;
        uint32_t ad = sb + GB_A(s) + (uint32_t)arow * 144 + (uint32_t)ahalf * 64;
#pragma unroll
        for (int j = 0; j < 4; ++j) cpa16(ad + j * 16, ar + k0 + j * 8);
        const __half* bsrc = g_w2h + ((size_t)e * FF + k0 + bk) * HD + n_base;
        uint32_t bd = sb + GB_B(s) + (uint32_t)bk * 272;
#pragma unroll
        for (int q = 0; q < 4; ++q)
            cpa16(bd + (bc + q * 4) * 16, bsrc + (bc + q * 4) * 8);
    };

    issue(0); CP_COMMIT();

    for (int c = 0; c < FF / 64; ++c) {
        CP_WAIT0();
        __syncthreads();
        if (c + 1 < FF / 64) issue(c + 1);
        CP_COMMIT();
        const int s = c & 1;
        const uint32_t aS = sb + GB_A(s), bS = sb + GB_B(s);
#pragma unroll
        for (int ks = 0; ks < 4; ++ks) {
            uint32_t a[2][4];
#pragma unroll
            for (int mf = 0; mf < 2; ++mf)
                ldsm4(a[mf], aS + aoff + (uint32_t)mf * (16 * 144) + (uint32_t)ks * 32);
#pragma unroll
            for (int pr = 0; pr < 4; ++pr) {
                uint32_t b[4];
                ldsm4t(b, bS + boff + (uint32_t)ks * (16 * 272) + (uint32_t)pr * 32);
#pragma unroll
                for (int sub = 0; sub < 2; ++sub) {
                    int nf = pr * 2 + sub;
#pragma unroll
                    for (int mf = 0; mf < 2; ++mf)
                        mma16816(acc[mf][nf], a[mf], b + sub * 2);
                }
            }
        }
    }

    // epilogue: weighted vector-reduction scatter (red.global.add.v2.f32)
#pragma unroll
    for (int mf = 0; mf < 2; ++mf) {
#pragma unroll
        for (int half = 0; half < 2; ++half) {
            int r = wm * 32 + mf * 16 + (lane >> 2) + half * 8;
            int grr = m_base + r;
            if (grr < cnt) {
                int tok = g_rowtok[e * CAP + grr];
                float w  = g_wslot[e * CAP + grr];
                float* op = out + (size_t)tok * HD + n_base + wn * 64 + (lane & 3) * 2;
#pragma unroll
                for (int nf = 0; nf < 8; ++nf)
                    red2(op + nf * 8, w * acc[mf][nf][half * 2], w * acc[mf][nf][half * 2 + 1]);
            }
        }
    }
}

// ---------------- 5) copy router logits into output tail ----------------
__global__ void copy_logits_kernel(float* __restrict__ dst) {
    int i = blockIdx.x * blockDim.x + threadIdx.x;
    int n = TOK * NE;
    for (; i < n; i += gridDim.x * blockDim.x) dst[i] = g_logits[i];
}

// ---------------- host launcher ----------------
extern "C" void kernel_launch(void* const* d_in, const int* in_sizes, int n_in,
                              void* d_out, int out_size) {
    const float* x  = (const float*)d_in[0];
    const float* wg = (const float*)d_in[1];
    const float* w1 = (const float*)d_in[2];
    const float* w3 = (const float*)d_in[3];
    const float* w2 = (const float*)d_in[4];
    float* out = (float*)d_out;

    cudaFuncSetAttribute(gemm_a_mma, cudaFuncAttributeMaxDynamicSharedMemorySize, GA_TOTAL);
    cudaFuncSetAttribute(gemm_b_mma, cudaFuncAttributeMaxDynamicSharedMemorySize, GB_TOTAL);

    router_cvt_kernel<<<RB + CVB, 256>>>(x, wg, w1, w3, w2);     // 0: router + fp16 converts + cnt reset
    topk_disp_zero_kernel<<<TKB + ZOB, 256>>>((float4*)out);     // 1: topk + dispatch + zero out
    dim3 ga(FF / 64, CAP / 128, NE);                             // (8, 8, 64)
    gemm_a_mma<<<ga, 256, GA_TOTAL>>>();                         // 2
    dim3 gb(HD / 128, CAP / 128, NE);                            // (8, 8, 64)
    gemm_b_mma<<<gb, 256, GB_TOTAL>>>(out);                      // 3 (profiled)

    if ((size_t)out_size >= (size_t)TOK * HD + (size_t)TOK * NE) {
        copy_logits_kernel<<<256, 256>>>(out + (size_t)TOK * HD);
    }
}

// round 11
// speedup vs baseline: 1.0039x; 1.0039x over previous
#include <cuda_runtime.h>
#include <cuda_fp16.h>
#include <math.h>
#include <stdint.h>

// Problem constants (B=2,S=2048,H=1024,E=64,K=8,F=512,cap=2.0)
#define TOK   4096
#define HD    1024
#define NE    64
#define KSEL  8
#define FF    512
#define NA    (TOK*KSEL)
#define CAP   1024

// ---------------- scratch (__device__ globals) ----------------
__device__ __align__(16) float g_logits[(size_t)TOK * NE];
__device__ int   g_rowtok[NE * CAP];
__device__ float g_wslot[NE * CAP];
__device__ int   g_cnt[NE];
__device__ __align__(16) __half g_xh [(size_t)TOK * HD];            // 8MB
__device__ __align__(16) __half g_w1h[(size_t)NE * HD * FF];        // 64MB
__device__ __align__(16) __half g_w3h[(size_t)NE * HD * FF];        // 64MB
__device__ __align__(16) __half g_w2h[(size_t)NE * FF * HD];        // 64MB
__device__ __align__(16) __half g_act[(size_t)NE * CAP * FF];       // 64MB

// ---------------- helpers ----------------
__device__ __forceinline__ uint32_t smem_u32(const void* p) {
    uint32_t a;
    asm("{ .reg .u64 t; cvta.to.shared.u64 t, %1; cvt.u32.u64 %0, t; }" : "=r"(a) : "l"(p));
    return a;
}
__device__ __forceinline__ void cpa16(uint32_t s, const void* g) {
    asm volatile("cp.async.cg.shared.global [%0], [%1], 16;" :: "r"(s), "l"(g));
}
#define CP_COMMIT() asm volatile("cp.async.commit_group;" ::: "memory")
#define CP_WAIT1()  asm volatile("cp.async.wait_group 1;" ::: "memory")
__device__ __forceinline__ void ldsm4(uint32_t* r, uint32_t addr) {
    asm volatile("ldmatrix.sync.aligned.m8n8.x4.shared.b16 {%0,%1,%2,%3}, [%4];"
                 : "=r"(r[0]), "=r"(r[1]), "=r"(r[2]), "=r"(r[3]) : "r"(addr));
}
__device__ __forceinline__ void ldsm4t(uint32_t* r, uint32_t addr) {
    asm volatile("ldmatrix.sync.aligned.m8n8.x4.trans.shared.b16 {%0,%1,%2,%3}, [%4];"
                 : "=r"(r[0]), "=r"(r[1]), "=r"(r[2]), "=r"(r[3]) : "r"(addr));
}
__device__ __forceinline__ void mma16816(float* c, const uint32_t* a, const uint32_t* b) {
    asm volatile("mma.sync.aligned.m16n8k16.row.col.f32.f16.f16.f32 "
                 "{%0,%1,%2,%3}, {%4,%5,%6,%7}, {%8,%9}, {%0,%1,%2,%3};"
                 : "+f"(c[0]), "+f"(c[1]), "+f"(c[2]), "+f"(c[3])
                 : "r"(a[0]), "r"(a[1]), "r"(a[2]), "r"(a[3]), "r"(b[0]), "r"(b[1]));
}
__device__ __forceinline__ uint32_t pkh(float a, float b) {
    __half2 h = __floats2half2_rn(a, b);
    return *(uint32_t*)&h;
}
__device__ __forceinline__ void red2(float* p, float a, float b) {
    asm volatile("red.global.add.v2.f32 [%0], {%1, %2};" :: "l"(p), "f"(a), "f"(b) : "memory");
}

// smem layouts (bytes), 3 stages, BK=64. A rows 144B; gemm_a B rows 144B; gemm_b B rows 272B.
#define GA_A(s)   ((s) * 18432)
#define GA_B1(s)  (55296 + (s) * 9216)
#define GA_B3(s)  (82944 + (s) * 9216)
#define GA_TOTAL  110592
#define GB_A(s)   ((s) * 18432)
#define GB_B(s)   (55296 + (s) * 17408)
#define GB_TOTAL  107520

// ---------------- 1) router logits + fp16 conversions (fused) ----------------
#define RT 8
#define RB (TOK / RT)          // 512 router blocks
#define CVB 1536               // conversion blocks
__global__ __launch_bounds__(256) void router_cvt_kernel(const float* __restrict__ x,
                                                         const float* __restrict__ wg,
                                                         const float* __restrict__ w1,
                                                         const float* __restrict__ w3,
                                                         const float* __restrict__ w2) {
    if (blockIdx.x >= RB) {
        const size_t N4 = (size_t)NE * HD * FF / 4;
        size_t i = (size_t)(blockIdx.x - RB) * 256 + threadIdx.x;
        size_t stride = (size_t)CVB * 256;
        for (; i < N4; i += stride) {
            float4 v = ((const float4*)w1)[i];
            ((uint2*)g_w1h)[i] = make_uint2(pkh(v.x, v.y), pkh(v.z, v.w));
            v = ((const float4*)w3)[i];
            ((uint2*)g_w3h)[i] = make_uint2(pkh(v.x, v.y), pkh(v.z, v.w));
            v = ((const float4*)w2)[i];
            ((uint2*)g_w2h)[i] = make_uint2(pkh(v.x, v.y), pkh(v.z, v.w));
        }
        return;
    }
    if (blockIdx.x == 0 && threadIdx.x < NE) g_cnt[threadIdx.x] = 0;
    __shared__ __align__(16) float xs[RT][HD];
    int t0 = blockIdx.x * RT;
    for (int i = threadIdx.x; i < RT * HD / 4; i += 256) {
        int r = i >> 8;
        int c = (i & 255) << 2;
        float4 v = *(const float4*)&x[(size_t)(t0 + r) * HD + c];
        *(float4*)&xs[r][c] = v;
        *(uint2*)&g_xh[(size_t)(t0 + r) * HD + c] = make_uint2(pkh(v.x, v.y), pkh(v.z, v.w));
    }
    __syncthreads();
    int e  = threadIdx.x & 63;
    int tg = threadIdx.x >> 6;
    float acc0 = 0.f, acc1 = 0.f;
#pragma unroll 4
    for (int j = 0; j < HD; ++j) {
        float w = wg[(size_t)j * NE + e];
        acc0 += w * xs[tg * 2 + 0][j];
        acc1 += w * xs[tg * 2 + 1][j];
    }
    g_logits[(size_t)(t0 + tg * 2 + 0) * NE + e] = acc0;
    g_logits[(size_t)(t0 + tg * 2 + 1) * NE + e] = acc1;
}

// ---------------- 2) topk + fused dispatch + zero_out (extra blocks) ----------------
#define TKB (TOK / 256)        // 16 topk blocks
#define ZOB (TOK * HD / 4 / 256)
__global__ __launch_bounds__(256) void topk_disp_zero_kernel(float4* __restrict__ outz) {
    if (blockIdx.x >= TKB) {
        int i = (blockIdx.x - TKB) * 256 + threadIdx.x;
        outz[i] = make_float4(0.f, 0.f, 0.f, 0.f);
        return;
    }
    int t = blockIdx.x * 256 + threadIdx.x;
    const float* l = g_logits + (size_t)t * NE;
    float m = -INFINITY;
    for (int e = 0; e < NE; ++e) m = fmaxf(m, l[e]);
    float s = 0.f;
    for (int e = 0; e < NE; ++e) s += expf(l[e] - m);
    unsigned long long mask = 0ull;
    float wv[KSEL]; int se[KSEL];
    float wsum = 0.f;
    for (int k = 0; k < KSEL; ++k) {
        float best = -INFINITY; int be = 0;
        for (int e = 0; e < NE; ++e) {
            if ((mask >> e) & 1ull) continue;
            float v = l[e];
            if (v > best) { best = v; be = e; }
        }
        mask |= (1ull << be);
        float p = expf(best - m) / s;
        wv[k] = p; se[k] = be; wsum += p;
    }
    float inv = 1.f / wsum;
    for (int k = 0; k < KSEL; ++k) {
        int e = se[k];
        int p = atomicAdd(&g_cnt[e], 1);
        if (p < CAP) {
            g_rowtok[e * CAP + p] = t;
            g_wslot[e * CAP + p]  = wv[k] * inv;
        }
    }
}

// ---------------- 3) GEMM-A: act = silu(x@w1)*(x@w3)  [fp16 mma, BK=64, 3-stage wait1, 2 CTA/SM] ----------------
// block 128m x 64n x BK64; 8 warps = 4m x 2n; warp tile 32x32 (dual acc)
__global__ __launch_bounds__(256, 2) void gemm_a_mma() {
    extern __shared__ char smc[];
    const uint32_t sb = smem_u32(smc);

    const int e = blockIdx.z;
    int cnt = g_cnt[e]; if (cnt > CAP) cnt = CAP;
    const int m_base = blockIdx.y * 128;
    if (m_base >= cnt) return;
    const int n_base = blockIdx.x * 64;

    const int tid = threadIdx.x, lane = tid & 31, wid = tid >> 5;
    const int wm = wid >> 1, wn = wid & 1;

    const int arow = tid >> 1, ahalf = tid & 1;
    int gr = m_base + arow; if (gr >= cnt) gr = cnt - 1;
    const __half* xr = g_xh + (size_t)g_rowtok[e * CAP + gr] * HD + ahalf * 32;
    const int bk = tid >> 2, bc = tid & 3;

    const uint32_t aoff = (uint32_t)(wm * 32 + (lane & 15)) * 144 + (uint32_t)(lane >> 4) * 16;
    const uint32_t boff = (uint32_t)(lane & 15) * 144 + (uint32_t)(lane >> 4) * 16 + (uint32_t)wn * 64;

    float acc1[2][4][4] = {}, acc3[2][4][4] = {};

    auto issue = [&](int cc) {
        int s = cc % 3, k0 = cc * 64;
        uint32_t ad = sb + GA_A(s) + (uint32_t)arow * 144 + (uint32_t)ahalf * 64;
#pragma unroll
        for (int j = 0; j < 4; ++j) cpa16(ad + j * 16, xr + k0 + j * 8);
        size_t ro = ((size_t)e * HD + k0 + bk) * FF + n_base;
        uint32_t b1d = sb + GA_B1(s) + (uint32_t)bk * 144;
        uint32_t b3d = sb + GA_B3(s) + (uint32_t)bk * 144;
#pragma unroll
        for (int q = 0; q < 2; ++q) {
            cpa16(b1d + (bc + q * 4) * 16, g_w1h + ro + (bc + q * 4) * 8);
            cpa16(b3d + (bc + q * 4) * 16, g_w3h + ro + (bc + q * 4) * 8);
        }
    };

    issue(0); CP_COMMIT();
    issue(1); CP_COMMIT();

    for (int c = 0; c < HD / 64; ++c) {
        CP_WAIT1();
        __syncthreads();
        if (c + 2 < HD / 64) issue(c + 2);
        CP_COMMIT();
        const int s = c % 3;
        const uint32_t aS = sb + GA_A(s), b1S = sb + GA_B1(s), b3S = sb + GA_B3(s);
#pragma unroll
        for (int ks = 0; ks < 4; ++ks) {
            uint32_t a[2][4];
#pragma unroll
            for (int mf = 0; mf < 2; ++mf)
                ldsm4(a[mf], aS + aoff + (uint32_t)mf * (16 * 144) + (uint32_t)ks * 32);
#pragma unroll
            for (int pr = 0; pr < 2; ++pr) {
                uint32_t o = boff + (uint32_t)ks * (16 * 144) + (uint32_t)pr * 32;
                uint32_t b1[4], b3[4];
                ldsm4t(b1, b1S + o); ldsm4t(b3, b3S + o);
#pragma unroll
                for (int sub = 0; sub < 2; ++sub) {
                    int nf = pr * 2 + sub;
#pragma unroll
                    for (int mf = 0; mf < 2; ++mf) {
                        mma16816(acc1[mf][nf], a[mf], b1 + sub * 2);
                        mma16816(acc3[mf][nf], a[mf], b3 + sub * 2);
                    }
                }
            }
        }
    }

    // epilogue: silu(g)*u -> fp16 act
#pragma unroll
    for (int mf = 0; mf < 2; ++mf) {
#pragma unroll
        for (int half = 0; half < 2; ++half) {
            int r = wm * 32 + mf * 16 + (lane >> 2) + half * 8;
            int grr = m_base + r;
            if (grr < cnt) {
                size_t rb = ((size_t)e * CAP + grr) * FF + n_base + wn * 32 + (lane & 3) * 2;
#pragma unroll
                for (int nf = 0; nf < 4; ++nf) {
                    float g0 = acc1[mf][nf][half * 2],     u0 = acc3[mf][nf][half * 2];
                    float g1 = acc1[mf][nf][half * 2 + 1], u1 = acc3[mf][nf][half * 2 + 1];
                    float a0 = (g0 / (1.f + expf(-g0))) * u0;
                    float a1 = (g1 / (1.f + expf(-g1))) * u1;
                    *(uint32_t*)&g_act[rb + nf * 8] = pkh(a0, a1);
                }
            }
        }
    }
}

// ---------------- 4) GEMM-B: out += w * (act @ w2)  [fp16 mma, BK=64, 3-stage wait1, red.v2] ----------------
// block 128m x 128n x BK64; 8 warps = 4m x 2n; warp tile 32x64
__global__ __launch_bounds__(256, 2) void gemm_b_mma(float* __restrict__ out) {
    extern __shared__ char smc[];
    const uint32_t sb = smem_u32(smc);

    const int e = blockIdx.z;
    int cnt = g_cnt[e]; if (cnt > CAP) cnt = CAP;
    const int m_base = blockIdx.y * 128;
    if (m_base >= cnt) return;
    const int n_base = blockIdx.x * 128;

    const int tid = threadIdx.x, lane = tid & 31, wid = tid >> 5;
    const int wm = wid >> 1, wn = wid & 1;

    const int arow = tid >> 1, ahalf = tid & 1;
    int gr = m_base + arow; if (gr >= cnt) gr = cnt - 1;
    const __half* ar = g_act + ((size_t)e * CAP + gr) * FF + ahalf * 32;
    const int bk = tid >> 2, bc = tid & 3;

    const uint32_t aoff = (uint32_t)(wm * 32 + (lane & 15)) * 144 + (uint32_t)(lane >> 4) * 16;
    const uint32_t boff = (uint32_t)(lane & 15) * 272 + (uint32_t)(lane >> 4) * 16 + (uint32_t)wn * 128;

    float acc[2][8][4] = {};

    auto issue = [&](int cc) {
        int s = cc % 3, k0 = cc * 64;
        uint32_t ad = sb + GB_A(s) + (uint32_t)arow * 144 + (uint32_t)ahalf * 64;
#pragma unroll
        for (int j = 0; j < 4; ++j) cpa16(ad + j * 16, ar + k0 + j * 8);
        const __half* bsrc = g_w2h + ((size_t)e * FF + k0 + bk) * HD + n_base;
        uint32_t bd = sb + GB_B(s) + (uint32_t)bk * 272;
#pragma unroll
        for (int q = 0; q < 4; ++q)
            cpa16(bd + (bc + q * 4) * 16, bsrc + (bc + q * 4) * 8);
    };

    issue(0); CP_COMMIT();
    issue(1); CP_COMMIT();

    for (int c = 0; c < FF / 64; ++c) {
        CP_WAIT1();
        __syncthreads();
        if (c + 2 < FF / 64) issue(c + 2);
        CP_COMMIT();
        const int s = c % 3;
        const uint32_t aS = sb + GB_A(s), bS = sb + GB_B(s);
#pragma unroll
        for (int ks = 0; ks < 4; ++ks) {
            uint32_t a[2][4];
#pragma unroll
            for (int mf = 0; mf < 2; ++mf)
                ldsm4(a[mf], aS + aoff + (uint32_t)mf * (16 * 144) + (uint32_t)ks * 32);
#pragma unroll
            for (int pr = 0; pr < 4; ++pr) {
                uint32_t b[4];
                ldsm4t(b, bS + boff + (uint32_t)ks * (16 * 272) + (uint32_t)pr * 32);
#pragma unroll
                for (int sub = 0; sub < 2; ++sub) {
                    int nf = pr * 2 + sub;
#pragma unroll
                    for (int mf = 0; mf < 2; ++mf)
                        mma16816(acc[mf][nf], a[mf], b + sub * 2);
                }
            }
        }
    }

    // epilogue: weighted vector-reduction scatter (red.global.add.v2.f32)
#pragma unroll
    for (int mf = 0; mf < 2; ++mf) {
#pragma unroll
        for (int half = 0; half < 2; ++half) {
            int r = wm * 32 + mf * 16 + (lane >> 2) + half * 8;
            int grr = m_base + r;
            if (grr < cnt) {
                int tok = g_rowtok[e * CAP + grr];
                float w  = g_wslot[e * CAP + grr];
                float* op = out + (size_t)tok * HD + n_base + wn * 64 + (lane & 3) * 2;
#pragma unroll
                for (int nf = 0; nf < 8; ++nf)
                    red2(op + nf * 8, w * acc[mf][nf][half * 2], w * acc[mf][nf][half * 2 + 1]);
            }
        }
    }
}

// ---------------- 5) copy router logits into output tail ----------------
__global__ void copy_logits_kernel(float* __restrict__ dst) {
    int i = blockIdx.x * blockDim.x + threadIdx.x;
    int n = TOK * NE;
    for (; i < n; i += gridDim.x * blockDim.x) dst[i] = g_logits[i];
}

// ---------------- host launcher ----------------
extern "C" void kernel_launch(void* const* d_in, const int* in_sizes, int n_in,
                              void* d_out, int out_size) {
    const float* x  = (const float*)d_in[0];
    const float* wg = (const float*)d_in[1];
    const float* w1 = (const float*)d_in[2];
    const float* w3 = (const float*)d_in[3];
    const float* w2 = (const float*)d_in[4];
    float* out = (float*)d_out;

    cudaFuncSetAttribute(gemm_a_mma, cudaFuncAttributeMaxDynamicSharedMemorySize, GA_TOTAL);
    cudaFuncSetAttribute(gemm_b_mma, cudaFuncAttributeMaxDynamicSharedMemorySize, GB_TOTAL);

    router_cvt_kernel<<<RB + CVB, 256>>>(x, wg, w1, w3, w2);     // 0
    topk_disp_zero_kernel<<<TKB + ZOB, 256>>>((float4*)out);     // 1
    if ((size_t)out_size >= (size_t)TOK * HD + (size_t)TOK * NE) {
        copy_logits_kernel<<<256, 256>>>(out + (size_t)TOK * HD); // 2
    }
    dim3 ga(FF / 64, CAP / 128, NE);                             // (8, 8, 64)
    gemm_a_mma<<<ga, 256, GA_TOTAL>>>();                         // 3 (profiled)
    dim3 gb(HD / 128, CAP / 128, NE);                            // (8, 8, 64)
    gemm_b_mma<<<gb, 256, GB_TOTAL>>>(out);                      // 4
}

// round 12
// speedup vs baseline: 1.0762x; 1.0721x over previous
#include <cuda_runtime.h>
#include <cuda_fp16.h>
#include <math.h>
#include <stdint.h>

// Problem constants (B=2,S=2048,H=1024,E=64,K=8,F=512,cap=2.0)
#define TOK   4096
#define HD    1024
#define NE    64
#define KSEL  8
#define FF    512
#define NA    (TOK*KSEL)
#define CAP   1024

// ---------------- scratch (__device__ globals) ----------------
__device__ __align__(16) float g_logits[(size_t)TOK * NE];
__device__ int   g_rowtok[NE * CAP];
__device__ float g_wslot[NE * CAP];
__device__ int   g_cnt[NE];
__device__ __align__(16) __half g_xh [(size_t)TOK * HD];            // 8MB
__device__ __align__(16) __half g_w1h[(size_t)NE * HD * FF];        // 64MB
__device__ __align__(16) __half g_w3h[(size_t)NE * HD * FF];        // 64MB
__device__ __align__(16) __half g_w2h[(size_t)NE * FF * HD];        // 64MB
__device__ __align__(16) __half g_act[(size_t)NE * CAP * FF];       // 64MB

// ---------------- helpers ----------------
__device__ __forceinline__ uint32_t smem_u32(const void* p) {
    uint32_t a;
    asm("{ .reg .u64 t; cvta.to.shared.u64 t, %1; cvt.u32.u64 %0, t; }" : "=r"(a) : "l"(p));
    return a;
}
__device__ __forceinline__ void cpa16(uint32_t s, const void* g) {
    asm volatile("cp.async.cg.shared.global [%0], [%1], 16;" :: "r"(s), "l"(g));
}
#define CP_COMMIT() asm volatile("cp.async.commit_group;" ::: "memory")
#define CP_WAIT2()  asm volatile("cp.async.wait_group 2;" ::: "memory")
#define CP_WAIT0()  asm volatile("cp.async.wait_group 0;" ::: "memory")
__device__ __forceinline__ void ldsm4(uint32_t* r, uint32_t addr) {
    asm volatile("ldmatrix.sync.aligned.m8n8.x4.shared.b16 {%0,%1,%2,%3}, [%4];"
                 : "=r"(r[0]), "=r"(r[1]), "=r"(r[2]), "=r"(r[3]) : "r"(addr));
}
__device__ __forceinline__ void ldsm4t(uint32_t* r, uint32_t addr) {
    asm volatile("ldmatrix.sync.aligned.m8n8.x4.trans.shared.b16 {%0,%1,%2,%3}, [%4];"
                 : "=r"(r[0]), "=r"(r[1]), "=r"(r[2]), "=r"(r[3]) : "r"(addr));
}
__device__ __forceinline__ void mma16816(float* c, const uint32_t* a, const uint32_t* b) {
    asm volatile("mma.sync.aligned.m16n8k16.row.col.f32.f16.f16.f32 "
                 "{%0,%1,%2,%3}, {%4,%5,%6,%7}, {%8,%9}, {%0,%1,%2,%3};"
                 : "+f"(c[0]), "+f"(c[1]), "+f"(c[2]), "+f"(c[3])
                 : "r"(a[0]), "r"(a[1]), "r"(a[2]), "r"(a[3]), "r"(b[0]), "r"(b[1]));
}
__device__ __forceinline__ uint32_t pkh(float a, float b) {
    __half2 h = __floats2half2_rn(a, b);
    return *(uint32_t*)&h;
}
__device__ __forceinline__ void red2(float* p, float a, float b) {
    asm volatile("red.global.add.v2.f32 [%0], {%1, %2};" :: "l"(p), "f"(a), "f"(b) : "memory");
}

// GEMM-A smem (BK=32, 4 stages): A rows 80B; B rows 144B.
#define GA_A(s)   ((s) * 10240)
#define GA_B1(s)  (40960 + (s) * 4608)
#define GA_B3(s)  (59392 + (s) * 4608)
#define GA_TOTAL  77824
// GEMM-B smem (BK=64, 2 stages): A rows 144B; B rows 272B.
#define GB_A(s)   ((s) * 18432)
#define GB_B(s)   (36864 + (s) * 17408)
#define GB_TOTAL  71680

// ---------------- 1) router logits + fp16 conversions (fused) ----------------
#define RT 8
#define RB (TOK / RT)          // 512 router blocks
#define CVB 1536               // conversion blocks
__global__ __launch_bounds__(256) void router_cvt_kernel(const float* __restrict__ x,
                                                         const float* __restrict__ wg,
                                                         const float* __restrict__ w1,
                                                         const float* __restrict__ w3,
                                                         const float* __restrict__ w2) {
    if (blockIdx.x >= RB) {
        const size_t N4 = (size_t)NE * HD * FF / 4;
        size_t i = (size_t)(blockIdx.x - RB) * 256 + threadIdx.x;
        size_t stride = (size_t)CVB * 256;
        for (; i < N4; i += stride) {
            float4 v = ((const float4*)w1)[i];
            ((uint2*)g_w1h)[i] = make_uint2(pkh(v.x, v.y), pkh(v.z, v.w));
            v = ((const float4*)w3)[i];
            ((uint2*)g_w3h)[i] = make_uint2(pkh(v.x, v.y), pkh(v.z, v.w));
            v = ((const float4*)w2)[i];
            ((uint2*)g_w2h)[i] = make_uint2(pkh(v.x, v.y), pkh(v.z, v.w));
        }
        return;
    }
    if (blockIdx.x == 0 && threadIdx.x < NE) g_cnt[threadIdx.x] = 0;
    __shared__ __align__(16) float xs[RT][HD];
    int t0 = blockIdx.x * RT;
    for (int i = threadIdx.x; i < RT * HD / 4; i += 256) {
        int r = i >> 8;
        int c = (i & 255) << 2;
        float4 v = *(const float4*)&x[(size_t)(t0 + r) * HD + c];
        *(float4*)&xs[r][c] = v;
        *(uint2*)&g_xh[(size_t)(t0 + r) * HD + c] = make_uint2(pkh(v.x, v.y), pkh(v.z, v.w));
    }
    __syncthreads();
    int e  = threadIdx.x & 63;
    int tg = threadIdx.x >> 6;
    float acc0 = 0.f, acc1 = 0.f;
#pragma unroll 4
    for (int j = 0; j < HD; ++j) {
        float w = wg[(size_t)j * NE + e];
        acc0 += w * xs[tg * 2 + 0][j];
        acc1 += w * xs[tg * 2 + 1][j];
    }
    g_logits[(size_t)(t0 + tg * 2 + 0) * NE + e] = acc0;
    g_logits[(size_t)(t0 + tg * 2 + 1) * NE + e] = acc1;
}

// ---------------- 2) topk + fused dispatch + zero_out (extra blocks) ----------------
#define TKB (TOK / 256)        // 16 topk blocks
#define ZOB (TOK * HD / 4 / 256)
__global__ __launch_bounds__(256) void topk_disp_zero_kernel(float4* __restrict__ outz) {
    if (blockIdx.x >= TKB) {
        int i = (blockIdx.x - TKB) * 256 + threadIdx.x;
        outz[i] = make_float4(0.f, 0.f, 0.f, 0.f);
        return;
    }
    int t = blockIdx.x * 256 + threadIdx.x;
    const float* l = g_logits + (size_t)t * NE;
    float m = -INFINITY;
    for (int e = 0; e < NE; ++e) m = fmaxf(m, l[e]);
    float s = 0.f;
    for (int e = 0; e < NE; ++e) s += expf(l[e] - m);
    unsigned long long mask = 0ull;
    float wv[KSEL]; int se[KSEL];
    float wsum = 0.f;
    for (int k = 0; k < KSEL; ++k) {
        float best = -INFINITY; int be = 0;
        for (int e = 0; e < NE; ++e) {
            if ((mask >> e) & 1ull) continue;
            float v = l[e];
            if (v > best) { best = v; be = e; }
        }
        mask |= (1ull << be);
        float p = expf(best - m) / s;
        wv[k] = p; se[k] = be; wsum += p;
    }
    float inv = 1.f / wsum;
    for (int k = 0; k < KSEL; ++k) {
        int e = se[k];
        int p = atomicAdd(&g_cnt[e], 1);
        if (p < CAP) {
            g_rowtok[e * CAP + p] = t;
            g_wslot[e * CAP + p]  = wv[k] * inv;
        }
    }
}

// ---------------- 3) GEMM-A: act = silu(x@w1)*(x@w3)  [fp16 mma, BK=32, 4-stage wait2] ----------------
// block 128m x 64n; 8 warps = 4m x 2n; warp tile 32x32 (dual acc)   [R8 measured 257us]
__global__ __launch_bounds__(256, 2) void gemm_a_mma() {
    extern __shared__ char smc[];
    const uint32_t sb = smem_u32(smc);

    const int e = blockIdx.z;
    int cnt = g_cnt[e]; if (cnt > CAP) cnt = CAP;
    const int m_base = blockIdx.y * 128;
    if (m_base >= cnt) return;
    const int n_base = blockIdx.x * 64;

    const int tid = threadIdx.x, lane = tid & 31, wid = tid >> 5;
    const int wm = wid >> 1, wn = wid & 1;

    const int arow = tid >> 1, ahalf = tid & 1;
    int gr = m_base + arow; if (gr >= cnt) gr = cnt - 1;
    const __half* xr = g_xh + (size_t)g_rowtok[e * CAP + gr] * HD + ahalf * 16;
    const int bk = tid >> 3, bc0 = tid & 7;

    const uint32_t aoff = (uint32_t)(wm * 32 + (lane & 15)) * 80 + (uint32_t)(lane >> 4) * 16;
    const uint32_t boff = (uint32_t)(lane & 15) * 144 + (uint32_t)(lane >> 4) * 16 + (uint32_t)wn * 64;

    float acc1[2][4][4] = {}, acc3[2][4][4] = {};

    auto issue = [&](int cc) {
        int s = cc & 3, k0 = cc * 32;
        uint32_t ad = sb + GA_A(s) + (uint32_t)arow * 80 + (uint32_t)ahalf * 32;
        cpa16(ad, xr + k0);
        cpa16(ad + 16, xr + k0 + 8);
        size_t ro = ((size_t)e * HD + k0 + bk) * FF + n_base + bc0 * 8;
        cpa16(sb + GA_B1(s) + (uint32_t)bk * 144 + bc0 * 16, g_w1h + ro);
        cpa16(sb + GA_B3(s) + (uint32_t)bk * 144 + bc0 * 16, g_w3h + ro);
    };

    issue(0); CP_COMMIT();
    issue(1); CP_COMMIT();
    issue(2); CP_COMMIT();

    for (int c = 0; c < HD / 32; ++c) {
        CP_WAIT2();
        __syncthreads();
        if (c + 3 < HD / 32) issue(c + 3);
        CP_COMMIT();
        const int s = c & 3;
        const uint32_t aS = sb + GA_A(s), b1S = sb + GA_B1(s), b3S = sb + GA_B3(s);
#pragma unroll
        for (int ks = 0; ks < 2; ++ks) {
            uint32_t a[2][4];
#pragma unroll
            for (int mf = 0; mf < 2; ++mf)
                ldsm4(a[mf], aS + aoff + (uint32_t)mf * (16 * 80) + (uint32_t)ks * 32);
#pragma unroll
            for (int pr = 0; pr < 2; ++pr) {
                uint32_t o = boff + (uint32_t)ks * (16 * 144) + (uint32_t)pr * 32;
                uint32_t b1[4], b3[4];
                ldsm4t(b1, b1S + o); ldsm4t(b3, b3S + o);
#pragma unroll
                for (int sub = 0; sub < 2; ++sub) {
                    int nf = pr * 2 + sub;
#pragma unroll
                    for (int mf = 0; mf < 2; ++mf) {
                        mma16816(acc1[mf][nf], a[mf], b1 + sub * 2);
                        mma16816(acc3[mf][nf], a[mf], b3 + sub * 2);
                    }
                }
            }
        }
    }

    // epilogue: silu(g)*u -> fp16 act
#pragma unroll
    for (int mf = 0; mf < 2; ++mf) {
#pragma unroll
        for (int half = 0; half < 2; ++half) {
            int r = wm * 32 + mf * 16 + (lane >> 2) + half * 8;
            int grr = m_base + r;
            if (grr < cnt) {
                size_t rb = ((size_t)e * CAP + grr) * FF + n_base + wn * 32 + (lane & 3) * 2;
#pragma unroll
                for (int nf = 0; nf < 4; ++nf) {
                    float g0 = acc1[mf][nf][half * 2],     u0 = acc3[mf][nf][half * 2];
                    float g1 = acc1[mf][nf][half * 2 + 1], u1 = acc3[mf][nf][half * 2 + 1];
                    float a0 = (g0 / (1.f + expf(-g0))) * u0;
                    float a1 = (g1 / (1.f + expf(-g1))) * u1;
                    *(uint32_t*)&g_act[rb + nf * 8] = pkh(a0, a1);
                }
            }
        }
    }
}

// ---------------- 4) GEMM-B: out += w * (act @ w2)  [fp16 mma, BK=64, 2-stage wait0, red.v2] ----------------
// block 128m x 128n; 8 warps = 4m x 2n; warp tile 32x64   [R10 measured 172us]
__global__ __launch_bounds__(256, 2) void gemm_b_mma(float* __restrict__ out) {
    extern __shared__ char smc[];
    const uint32_t sb = smem_u32(smc);

    const int e = blockIdx.z;
    int cnt = g_cnt[e]; if (cnt > CAP) cnt = CAP;
    const int m_base = blockIdx.y * 128;
    if (m_base >= cnt) return;
    const int n_base = blockIdx.x * 128;

    const int tid = threadIdx.x, lane = tid & 31, wid = tid >> 5;
    const int wm = wid >> 1, wn = wid & 1;

    const int arow = tid >> 1, ahalf = tid & 1;
    int gr = m_base + arow; if (gr >= cnt) gr = cnt - 1;
    const __half* ar = g_act + ((size_t)e * CAP + gr) * FF + ahalf * 32;
    const int bk = tid >> 2, bc = tid & 3;

    const uint32_t aoff = (uint32_t)(wm * 32 + (lane & 15)) * 144 + (uint32_t)(lane >> 4) * 16;
    const uint32_t boff = (uint32_t)(lane & 15) * 272 + (uint32_t)(lane >> 4) * 16 + (uint32_t)wn * 128;

    float acc[2][8][4] = {};

    auto issue = [&](int cc) {
        int s = cc & 1, k0 = cc * 64;
        uint32_t ad = sb + GB_A(s) + (uint32_t)arow * 144 + (uint32_t)ahalf * 64;
#pragma unroll
        for (int j = 0; j < 4; ++j) cpa16(ad + j * 16, ar + k0 + j * 8);
        const __half* bsrc = g_w2h + ((size_t)e * FF + k0 + bk) * HD + n_base;
        uint32_t bd = sb + GB_B(s) + (uint32_t)bk * 272;
#pragma unroll
        for (int q = 0; q < 4; ++q)
            cpa16(bd + (bc + q * 4) * 16, bsrc + (bc + q * 4) * 8);
    };

    issue(0); CP_COMMIT();

    for (int c = 0; c < FF / 64; ++c) {
        CP_WAIT0();
        __syncthreads();
        if (c + 1 < FF / 64) issue(c + 1);
        CP_COMMIT();
        const int s = c & 1;
        const uint32_t aS = sb + GB_A(s), bS = sb + GB_B(s);
#pragma unroll
        for (int ks = 0; ks < 4; ++ks) {
            uint32_t a[2][4];
#pragma unroll
            for (int mf = 0; mf < 2; ++mf)
                ldsm4(a[mf], aS + aoff + (uint32_t)mf * (16 * 144) + (uint32_t)ks * 32);
#pragma unroll
            for (int pr = 0; pr < 4; ++pr) {
                uint32_t b[4];
                ldsm4t(b, bS + boff + (uint32_t)ks * (16 * 272) + (uint32_t)pr * 32);
#pragma unroll
                for (int sub = 0; sub < 2; ++sub) {
                    int nf = pr * 2 + sub;
#pragma unroll
                    for (int mf = 0; mf < 2; ++mf)
                        mma16816(acc[mf][nf], a[mf], b + sub * 2);
                }
            }
        }
    }

    // epilogue: weighted vector-reduction scatter (red.global.add.v2.f32)
#pragma unroll
    for (int mf = 0; mf < 2; ++mf) {
#pragma unroll
        for (int half = 0; half < 2; ++half) {
            int r = wm * 32 + mf * 16 + (lane >> 2) + half * 8;
            int grr = m_base + r;
            if (grr < cnt) {
                int tok = g_rowtok[e * CAP + grr];
                float w  = g_wslot[e * CAP + grr];
                float* op = out + (size_t)tok * HD + n_base + wn * 64 + (lane & 3) * 2;
#pragma unroll
                for (int nf = 0; nf < 8; ++nf)
                    red2(op + nf * 8, w * acc[mf][nf][half * 2], w * acc[mf][nf][half * 2 + 1]);
            }
        }
    }
}

// ---------------- 5) copy router logits into output tail ----------------
__global__ void copy_logits_kernel(float* __restrict__ dst) {
    int i = blockIdx.x * blockDim.x + threadIdx.x;
    int n = TOK * NE;
    for (; i < n; i += gridDim.x * blockDim.x) dst[i] = g_logits[i];
}

// ---------------- host launcher ----------------
extern "C" void kernel_launch(void* const* d_in, const int* in_sizes, int n_in,
                              void* d_out, int out_size) {
    const float* x  = (const float*)d_in[0];
    const float* wg = (const float*)d_in[1];
    const float* w1 = (const float*)d_in[2];
    const float* w3 = (const float*)d_in[3];
    const float* w2 = (const float*)d_in[4];
    float* out = (float*)d_out;

    cudaFuncSetAttribute(gemm_a_mma, cudaFuncAttributeMaxDynamicSharedMemorySize, GA_TOTAL);
    cudaFuncSetAttribute(gemm_b_mma, cudaFuncAttributeMaxDynamicSharedMemorySize, GB_TOTAL);

    router_cvt_kernel<<<RB + CVB, 256>>>(x, wg, w1, w3, w2);     // 0
    topk_disp_zero_kernel<<<TKB + ZOB, 256>>>((float4*)out);     // 1
    if ((size_t)out_size >= (size_t)TOK * HD + (size_t)TOK * NE) {
        copy_logits_kernel<<<256, 256>>>(out + (size_t)TOK * HD); // 2
    }
    dim3 ga(FF / 64, CAP / 128, NE);                             // (8, 8, 64)
    gemm_a_mma<<<ga, 256, GA_TOTAL>>>();                         // 3 (profiled)
    dim3 gb(HD / 128, CAP / 128, NE);                            // (8, 8, 64)
    gemm_b_mma<<<gb, 256, GB_TOTAL>>>(out);                      // 4
}

// round 13
// speedup vs baseline: 1.1261x; 1.0464x over previous
#include <cuda_runtime.h>
#include <cuda_fp16.h>
#include <math.h>
#include <stdint.h>

// Problem constants (B=2,S=2048,H=1024,E=64,K=8,F=512,cap=2.0)
#define TOK   4096
#define HD    1024
#define NE    64
#define KSEL  8
#define FF    512
#define NA    (TOK*KSEL)
#define CAP   1024

// ---------------- scratch (__device__ globals) ----------------
__device__ __align__(16) float g_logits[(size_t)TOK * NE];
__device__ int   g_rowtok[NE * CAP];
__device__ float g_wslot[NE * CAP];
__device__ int   g_cnt[NE];
__device__ __align__(16) __half g_xh [(size_t)TOK * HD];            // 8MB
__device__ __align__(16) __half g_w1h[(size_t)NE * HD * FF];        // 64MB
__device__ __align__(16) __half g_w3h[(size_t)NE * HD * FF];        // 64MB
__device__ __align__(16) __half g_w2h[(size_t)NE * FF * HD];        // 64MB
__device__ __align__(16) __half g_act[(size_t)NE * CAP * FF];       // 64MB

// ---------------- helpers ----------------
__device__ __forceinline__ uint32_t smem_u32(const void* p) {
    uint32_t a;
    asm("{ .reg .u64 t; cvta.to.shared.u64 t, %1; cvt.u32.u64 %0, t; }" : "=r"(a) : "l"(p));
    return a;
}
__device__ __forceinline__ void cpa16(uint32_t s, const void* g) {
    asm volatile("cp.async.cg.shared.global [%0], [%1], 16;" :: "r"(s), "l"(g));
}
#define CP_COMMIT() asm volatile("cp.async.commit_group;" ::: "memory")
#define CP_WAIT2()  asm volatile("cp.async.wait_group 2;" ::: "memory")
__device__ __forceinline__ void ldsm4(uint32_t* r, uint32_t addr) {
    asm volatile("ldmatrix.sync.aligned.m8n8.x4.shared.b16 {%0,%1,%2,%3}, [%4];"
                 : "=r"(r[0]), "=r"(r[1]), "=r"(r[2]), "=r"(r[3]) : "r"(addr));
}
__device__ __forceinline__ void ldsm4t(uint32_t* r, uint32_t addr) {
    asm volatile("ldmatrix.sync.aligned.m8n8.x4.trans.shared.b16 {%0,%1,%2,%3}, [%4];"
                 : "=r"(r[0]), "=r"(r[1]), "=r"(r[2]), "=r"(r[3]) : "r"(addr));
}
__device__ __forceinline__ void mma16816(float* c, const uint32_t* a, const uint32_t* b) {
    asm volatile("mma.sync.aligned.m16n8k16.row.col.f32.f16.f16.f32 "
                 "{%0,%1,%2,%3}, {%4,%5,%6,%7}, {%8,%9}, {%0,%1,%2,%3};"
                 : "+f"(c[0]), "+f"(c[1]), "+f"(c[2]), "+f"(c[3])
                 : "r"(a[0]), "r"(a[1]), "r"(a[2]), "r"(a[3]), "r"(b[0]), "r"(b[1]));
}
__device__ __forceinline__ uint32_t pkh(float a, float b) {
    __half2 h = __floats2half2_rn(a, b);
    return *(uint32_t*)&h;
}
__device__ __forceinline__ void red2(float* p, float a, float b) {
    asm volatile("red.global.add.v2.f32 [%0], {%1, %2};" :: "l"(p), "f"(a), "f"(b) : "memory");
}

// GEMM-A smem (BK=32, 4 stages): A rows 80B; B rows 144B.
#define GA_A(s)   ((s) * 10240)
#define GA_B1(s)  (40960 + (s) * 4608)
#define GA_B3(s)  (59392 + (s) * 4608)
#define GA_TOTAL  77824
// GEMM-B smem (BK=32, 4 stages): A rows 80B; B rows 272B.
#define GB_A(s)   ((s) * 10240)
#define GB_B(s)   (40960 + (s) * 8704)
#define GB_TOTAL  75776

// ---------------- 1) router logits + fp16 conversions (fused) ----------------
#define RT 8
#define RB (TOK / RT)          // 512 router blocks
#define CVB 1536               // conversion blocks
__global__ __launch_bounds__(256) void router_cvt_kernel(const float* __restrict__ x,
                                                         const float* __restrict__ wg,
                                                         const float* __restrict__ w1,
                                                         const float* __restrict__ w3,
                                                         const float* __restrict__ w2) {
    if (blockIdx.x >= RB) {
        const size_t N4 = (size_t)NE * HD * FF / 4;
        size_t i = (size_t)(blockIdx.x - RB) * 256 + threadIdx.x;
        size_t stride = (size_t)CVB * 256;
        for (; i < N4; i += stride) {
            float4 v = ((const float4*)w1)[i];
            ((uint2*)g_w1h)[i] = make_uint2(pkh(v.x, v.y), pkh(v.z, v.w));
            v = ((const float4*)w3)[i];
            ((uint2*)g_w3h)[i] = make_uint2(pkh(v.x, v.y), pkh(v.z, v.w));
            v = ((const float4*)w2)[i];
            ((uint2*)g_w2h)[i] = make_uint2(pkh(v.x, v.y), pkh(v.z, v.w));
        }
        return;
    }
    if (blockIdx.x == 0 && threadIdx.x < NE) g_cnt[threadIdx.x] = 0;
    __shared__ __align__(16) float xs[RT][HD];
    int t0 = blockIdx.x * RT;
    for (int i = threadIdx.x; i < RT * HD / 4; i += 256) {
        int r = i >> 8;
        int c = (i & 255) << 2;
        float4 v = *(const float4*)&x[(size_t)(t0 + r) * HD + c];
        *(float4*)&xs[r][c] = v;
        *(uint2*)&g_xh[(size_t)(t0 + r) * HD + c] = make_uint2(pkh(v.x, v.y), pkh(v.z, v.w));
    }
    __syncthreads();
    int e  = threadIdx.x & 63;
    int tg = threadIdx.x >> 6;
    float acc0 = 0.f, acc1 = 0.f;
#pragma unroll 4
    for (int j = 0; j < HD; ++j) {
        float w = wg[(size_t)j * NE + e];
        acc0 += w * xs[tg * 2 + 0][j];
        acc1 += w * xs[tg * 2 + 1][j];
    }
    g_logits[(size_t)(t0 + tg * 2 + 0) * NE + e] = acc0;
    g_logits[(size_t)(t0 + tg * 2 + 1) * NE + e] = acc1;
}

// ---------------- 2) topk + dispatch + zero_out + copy_logits (fused blocks) ----------------
#define TKB (TOK / 256)                 // 16 topk blocks
#define ZOB (TOK * HD / 4 / 256)        // 4096 zero blocks
#define CLB (TOK * NE / 4 / 256)        // 256 logit-copy blocks
__global__ __launch_bounds__(256) void topk_disp_zero_kernel(float4* __restrict__ outz,
                                                             float4* __restrict__ logit_dst,
                                                             int do_logits) {
    if (blockIdx.x >= TKB + ZOB) {
        if (do_logits) {
            int i = (blockIdx.x - TKB - ZOB) * 256 + threadIdx.x;
            logit_dst[i] = ((const float4*)g_logits)[i];
        }
        return;
    }
    if (blockIdx.x >= TKB) {
        int i = (blockIdx.x - TKB) * 256 + threadIdx.x;
        outz[i] = make_float4(0.f, 0.f, 0.f, 0.f);
        return;
    }
    int t = blockIdx.x * 256 + threadIdx.x;
    const float* l = g_logits + (size_t)t * NE;
    float m = -INFINITY;
    for (int e = 0; e < NE; ++e) m = fmaxf(m, l[e]);
    float s = 0.f;
    for (int e = 0; e < NE; ++e) s += expf(l[e] - m);
    unsigned long long mask = 0ull;
    float wv[KSEL]; int se[KSEL];
    float wsum = 0.f;
    for (int k = 0; k < KSEL; ++k) {
        float best = -INFINITY; int be = 0;
        for (int e = 0; e < NE; ++e) {
            if ((mask >> e) & 1ull) continue;
            float v = l[e];
            if (v > best) { best = v; be = e; }
        }
        mask |= (1ull << be);
        float p = expf(best - m) / s;
        wv[k] = p; se[k] = be; wsum += p;
    }
    float inv = 1.f / wsum;
    for (int k = 0; k < KSEL; ++k) {
        int e = se[k];
        int p = atomicAdd(&g_cnt[e], 1);
        if (p < CAP) {
            g_rowtok[e * CAP + p] = t;
            g_wslot[e * CAP + p]  = wv[k] * inv;
        }
    }
}

// ---------------- 3) GEMM-A: act = silu(x@w1)*(x@w3)  [fp16 mma, BK=32, 4-stage wait2] ----------------
// block 128m x 64n; 8 warps = 4m x 2n; warp tile 32x32 (dual acc)
__global__ __launch_bounds__(256, 2) void gemm_a_mma() {
    extern __shared__ char smc[];
    const uint32_t sb = smem_u32(smc);

    const int e = blockIdx.z;
    int cnt = g_cnt[e]; if (cnt > CAP) cnt = CAP;
    const int m_base = blockIdx.y * 128;
    if (m_base >= cnt) return;
    const int n_base = blockIdx.x * 64;

    const int tid = threadIdx.x, lane = tid & 31, wid = tid >> 5;
    const int wm = wid >> 1, wn = wid & 1;

    const int arow = tid >> 1, ahalf = tid & 1;
    int gr = m_base + arow; if (gr >= cnt) gr = cnt - 1;
    const __half* xr = g_xh + (size_t)g_rowtok[e * CAP + gr] * HD + ahalf * 16;
    const int bk = tid >> 3, bc0 = tid & 7;

    const uint32_t aoff = (uint32_t)(wm * 32 + (lane & 15)) * 80 + (uint32_t)(lane >> 4) * 16;
    const uint32_t boff = (uint32_t)(lane & 15) * 144 + (uint32_t)(lane >> 4) * 16 + (uint32_t)wn * 64;

    float acc1[2][4][4] = {}, acc3[2][4][4] = {};

    auto issue = [&](int cc) {
        int s = cc & 3, k0 = cc * 32;
        uint32_t ad = sb + GA_A(s) + (uint32_t)arow * 80 + (uint32_t)ahalf * 32;
        cpa16(ad, xr + k0);
        cpa16(ad + 16, xr + k0 + 8);
        size_t ro = ((size_t)e * HD + k0 + bk) * FF + n_base + bc0 * 8;
        cpa16(sb + GA_B1(s) + (uint32_t)bk * 144 + bc0 * 16, g_w1h + ro);
        cpa16(sb + GA_B3(s) + (uint32_t)bk * 144 + bc0 * 16, g_w3h + ro);
    };

    issue(0); CP_COMMIT();
    issue(1); CP_COMMIT();
    issue(2); CP_COMMIT();

    for (int c = 0; c < HD / 32; ++c) {
        CP_WAIT2();
        __syncthreads();
        if (c + 3 < HD / 32) issue(c + 3);
        CP_COMMIT();
        const int s = c & 3;
        const uint32_t aS = sb + GA_A(s), b1S = sb + GA_B1(s), b3S = sb + GA_B3(s);
#pragma unroll
        for (int ks = 0; ks < 2; ++ks) {
            uint32_t a[2][4];
#pragma unroll
            for (int mf = 0; mf < 2; ++mf)
                ldsm4(a[mf], aS + aoff + (uint32_t)mf * (16 * 80) + (uint32_t)ks * 32);
#pragma unroll
            for (int pr = 0; pr < 2; ++pr) {
                uint32_t o = boff + (uint32_t)ks * (16 * 144) + (uint32_t)pr * 32;
                uint32_t b1[4], b3[4];
                ldsm4t(b1, b1S + o); ldsm4t(b3, b3S + o);
#pragma unroll
                for (int sub = 0; sub < 2; ++sub) {
                    int nf = pr * 2 + sub;
#pragma unroll
                    for (int mf = 0; mf < 2; ++mf) {
                        mma16816(acc1[mf][nf], a[mf], b1 + sub * 2);
                        mma16816(acc3[mf][nf], a[mf], b3 + sub * 2);
                    }
                }
            }
        }
    }

    // epilogue: silu(g)*u -> fp16 act
#pragma unroll
    for (int mf = 0; mf < 2; ++mf) {
#pragma unroll
        for (int half = 0; half < 2; ++half) {
            int r = wm * 32 + mf * 16 + (lane >> 2) + half * 8;
            int grr = m_base + r;
            if (grr < cnt) {
                size_t rb = ((size_t)e * CAP + grr) * FF + n_base + wn * 32 + (lane & 3) * 2;
#pragma unroll
                for (int nf = 0; nf < 4; ++nf) {
                    float g0 = acc1[mf][nf][half * 2],     u0 = acc3[mf][nf][half * 2];
                    float g1 = acc1[mf][nf][half * 2 + 1], u1 = acc3[mf][nf][half * 2 + 1];
                    float a0 = (g0 / (1.f + expf(-g0))) * u0;
                    float a1 = (g1 / (1.f + expf(-g1))) * u1;
                    *(uint32_t*)&g_act[rb + nf * 8] = pkh(a0, a1);
                }
            }
        }
    }
}

// ---------------- 4) GEMM-B: out += w * (act @ w2)  [fp16 mma, BK=32, 4-stage wait2, red.v2] ----------------
// block 128m x 128n; 8 warps = 4m x 2n; warp tile 32x64
__global__ __launch_bounds__(256, 2) void gemm_b_mma(float* __restrict__ out) {
    extern __shared__ char smc[];
    const uint32_t sb = smem_u32(smc);

    const int e = blockIdx.z;
    int cnt = g_cnt[e]; if (cnt > CAP) cnt = CAP;
    const int m_base = blockIdx.y * 128;
    if (m_base >= cnt) return;
    const int n_base = blockIdx.x * 128;

    const int tid = threadIdx.x, lane = tid & 31, wid = tid >> 5;
    const int wm = wid >> 1, wn = wid & 1;

    const int arow = tid >> 1, ahalf = tid & 1;
    int gr = m_base + arow; if (gr >= cnt) gr = cnt - 1;
    const __half* ar = g_act + ((size_t)e * CAP + gr) * FF + ahalf * 16;
    const int bk = tid >> 3, bc0 = tid & 7;

    const uint32_t aoff = (uint32_t)(wm * 32 + (lane & 15)) * 80 + (uint32_t)(lane >> 4) * 16;
    const uint32_t boff = (uint32_t)(lane & 15) * 272 + (uint32_t)(lane >> 4) * 16 + (uint32_t)wn * 128;

    float acc[2][8][4] = {};

    auto issue = [&](int cc) {
        int s = cc & 3, k0 = cc * 32;
        uint32_t ad = sb + GB_A(s) + (uint32_t)arow * 80 + (uint32_t)ahalf * 32;
        cpa16(ad, ar + k0);
        cpa16(ad + 16, ar + k0 + 8);
        const __half* bsrc = g_w2h + ((size_t)e * FF + k0 + bk) * HD + n_base;
        uint32_t bd = sb + GB_B(s) + (uint32_t)bk * 272;
        cpa16(bd + bc0 * 16,       bsrc + bc0 * 8);
        cpa16(bd + (bc0 + 8) * 16, bsrc + (bc0 + 8) * 8);
    };

    issue(0); CP_COMMIT();
    issue(1); CP_COMMIT();
    issue(2); CP_COMMIT();

    for (int c = 0; c < FF / 32; ++c) {
        CP_WAIT2();
        __syncthreads();
        if (c + 3 < FF / 32) issue(c + 3);
        CP_COMMIT();
        const int s = c & 3;
        const uint32_t aS = sb + GB_A(s), bS = sb + GB_B(s);
#pragma unroll
        for (int ks = 0; ks < 2; ++ks) {
            uint32_t a[2][4];
#pragma unroll
            for (int mf = 0; mf < 2; ++mf)
                ldsm4(a[mf], aS + aoff + (uint32_t)mf * (16 * 80) + (uint32_t)ks * 32);
#pragma unroll
            for (int pr = 0; pr < 4; ++pr) {
                uint32_t b[4];
                ldsm4t(b, bS + boff + (uint32_t)ks * (16 * 272) + (uint32_t)pr * 32);
#pragma unroll
                for (int sub = 0; sub < 2; ++sub) {
                    int nf = pr * 2 + sub;
#pragma unroll
                    for (int mf = 0; mf < 2; ++mf)
                        mma16816(acc[mf][nf], a[mf], b + sub * 2);
                }
            }
        }
    }

    // epilogue: weighted vector-reduction scatter (red.global.add.v2.f32)
#pragma unroll
    for (int mf = 0; mf < 2; ++mf) {
#pragma unroll
        for (int half = 0; half < 2; ++half) {
            int r = wm * 32 + mf * 16 + (lane >> 2) + half * 8;
            int grr = m_base + r;
            if (grr < cnt) {
                int tok = g_rowtok[e * CAP + grr];
                float w  = g_wslot[e * CAP + grr];
                float* op = out + (size_t)tok * HD + n_base + wn * 64 + (lane & 3) * 2;
#pragma unroll
                for (int nf = 0; nf < 8; ++nf)
                    red2(op + nf * 8, w * acc[mf][nf][half * 2], w * acc[mf][nf][half * 2 + 1]);
            }
        }
    }
}

// ---------------- host launcher ----------------
extern "C" void kernel_launch(void* const* d_in, const int* in_sizes, int n_in,
                              void* d_out, int out_size) {
    const float* x  = (const float*)d_in[0];
    const float* wg = (const float*)d_in[1];
    const float* w1 = (const float*)d_in[2];
    const float* w3 = (const float*)d_in[3];
    const float* w2 = (const float*)d_in[4];
    float* out = (float*)d_out;

    cudaFuncSetAttribute(gemm_a_mma, cudaFuncAttributeMaxDynamicSharedMemorySize, GA_TOTAL);
    cudaFuncSetAttribute(gemm_b_mma, cudaFuncAttributeMaxDynamicSharedMemorySize, GB_TOTAL);

    int do_logits = ((size_t)out_size >= (size_t)TOK * HD + (size_t)TOK * NE) ? 1 : 0;

    router_cvt_kernel<<<RB + CVB, 256>>>(x, wg, w1, w3, w2);               // 0
    topk_disp_zero_kernel<<<TKB + ZOB + CLB, 256>>>((float4*)out,
        (float4*)(out + (size_t)TOK * HD), do_logits);                     // 1
    dim3 ga(FF / 64, CAP / 128, NE);                                       // (8, 8, 64)
    gemm_a_mma<<<ga, 256, GA_TOTAL>>>();                                   // 2
    dim3 gb(HD / 128, CAP / 128, NE);                                      // (8, 8, 64)
    gemm_b_mma<<<gb, 256, GB_TOTAL>>>(out);                                // 3 (profiled)
}